// round 1
// baseline (speedup 1.0000x reference)
#include <cuda_runtime.h>
#include <math.h>

// ---------------- problem constants ----------------
#define NB   4           // batch
#define NT   1024        // seq len
#define NC   768         // channels
#define NH   12          // heads
#define NHD  64          // head dim
#define NL   12          // layers
#define NV   50257       // vocab
#define NBT  (NB*NT)     // 4096 rows
#define NBTV (NBT*NV)    // 205852672 logits elements

// ---------------- scratch (static device globals; no runtime allocation) ----
__device__ float g_x  [NBT*NC];      // residual stream
__device__ float g_h  [NBT*NC];      // layernorm output
__device__ float g_qkv[NBT*3*NC];    // qkv projections
__device__ float g_att[NBT*NC];      // attention output
__device__ float g_fch[NBT*4*NC];    // mlp hidden
__device__ float g_logits_scratch[NBTV]; // used only if d_out can't hold logits
__device__ float g_loss_sum;
__device__ float g_loss_cnt;

// ---------------- small kernels ----------------
__global__ void k_zero_loss(float* s, float* c) { *s = 0.f; *c = 0.f; }

__global__ void k_embed(const int* __restrict__ idx,
                        const float* __restrict__ wte,
                        const float* __restrict__ wpe,
                        float* __restrict__ x)
{
    int i = blockIdx.x * blockDim.x + threadIdx.x;
    if (i >= NBT * NC) return;
    int c  = i % NC;
    int bt = i / NC;
    int t  = bt % NT;
    x[i] = wte[(long long)idx[bt] * NC + c] + wpe[t * NC + c];
}

// one block per row, 256 threads
__global__ void k_layernorm(const float* __restrict__ x,
                            const float* __restrict__ w,
                            const float* __restrict__ b,
                            float* __restrict__ out)
{
    int row = blockIdx.x;
    int tid = threadIdx.x;
    const float* xr = x + (long long)row * NC;
    __shared__ float red[256];

    float s = 0.f;
    for (int i = tid; i < NC; i += 256) s += xr[i];
    red[tid] = s; __syncthreads();
    for (int o = 128; o > 0; o >>= 1) { if (tid < o) red[tid] += red[tid + o]; __syncthreads(); }
    float mu = red[0] * (1.0f / NC);
    __syncthreads();

    float v = 0.f;
    for (int i = tid; i < NC; i += 256) { float d = xr[i] - mu; v += d * d; }
    red[tid] = v; __syncthreads();
    for (int o = 128; o > 0; o >>= 1) { if (tid < o) red[tid] += red[tid + o]; __syncthreads(); }
    float rstd = rsqrtf(red[0] * (1.0f / NC) + 1e-5f);
    __syncthreads();

    float* orow = out + (long long)row * NC;
    for (int i = tid; i < NC; i += 256)
        orow[i] = (xr[i] - mu) * rstd * w[i] + b[i];
}

// ---------------- tiled SGEMM: C[M,N] = A[M,K] @ W[K,N] (+bias)(+res)(gelu) --
// BM=64 BN=64 BK=16, 256 threads, 4x4 per thread.
// Requires: M % 64 == 0, K % 16 == 0. N arbitrary (guarded).
__global__ void k_gemm(const float* __restrict__ A,
                       const float* __restrict__ W,
                       const float* __restrict__ bias,   // may be null
                       const float* __restrict__ res,    // may be null
                       float* __restrict__ C,
                       int M, int N, int K, int act)     // act: 0 none, 1 gelu
{
    __shared__ float As[16][64];
    __shared__ float Bs[16][64];

    int bn = blockIdx.x * 64;
    int bm = blockIdx.y * 64;
    int tid = threadIdx.x;            // 0..255
    int tx = tid & 15;                // col group
    int ty = tid >> 4;                // row group

    float acc[4][4];
    #pragma unroll
    for (int i = 0; i < 4; i++)
        #pragma unroll
        for (int j = 0; j < 4; j++) acc[i][j] = 0.f;

    for (int k0 = 0; k0 < K; k0 += 16) {
        // load A tile transposed: As[k][m]
        #pragma unroll
        for (int it = 0; it < 4; it++) {
            int i = tid + it * 256;          // 0..1023
            int m = i >> 4, k = i & 15;
            As[k][m] = A[(long long)(bm + m) * K + k0 + k];
        }
        // load W tile: Bs[k][n]
        #pragma unroll
        for (int it = 0; it < 4; it++) {
            int i = tid + it * 256;
            int k = i >> 6, n = i & 63;
            int gn = bn + n;
            Bs[k][n] = (gn < N) ? W[(long long)(k0 + k) * N + gn] : 0.f;
        }
        __syncthreads();
        #pragma unroll
        for (int kk = 0; kk < 16; kk++) {
            float ar[4], br[4];
            #pragma unroll
            for (int i = 0; i < 4; i++) ar[i] = As[kk][ty * 4 + i];
            #pragma unroll
            for (int j = 0; j < 4; j++) br[j] = Bs[kk][tx * 4 + j];
            #pragma unroll
            for (int i = 0; i < 4; i++)
                #pragma unroll
                for (int j = 0; j < 4; j++)
                    acc[i][j] += ar[i] * br[j];
        }
        __syncthreads();
    }

    #pragma unroll
    for (int i = 0; i < 4; i++) {
        int m = bm + ty * 4 + i;
        #pragma unroll
        for (int j = 0; j < 4; j++) {
            int n = bn + tx * 4 + j;
            if (n < N) {
                float v = acc[i][j];
                if (bias) v += bias[n];
                if (res)  v += res[(long long)m * N + n];
                if (act == 1) {
                    float u = v;
                    v = 0.5f * u * (1.0f + tanhf(0.7978845608028654f *
                                                 (u + 0.044715f * u * u * u)));
                }
                C[(long long)m * N + n] = v;
            }
        }
    }
}

// ---------------- fused causal attention ----------------
// grid (T, H, B), 256 threads/block. One query row per block.
__global__ void k_attn(const float* __restrict__ qkv, float* __restrict__ y)
{
    int qi = blockIdx.x;
    int hh = blockIdx.y;
    int b  = blockIdx.z;
    int tid = threadIdx.x;

    __shared__ float qs[NHD];
    __shared__ float sc[NT];
    __shared__ float red[256];
    __shared__ float part[4][NHD];

    const float* base = qkv + (long long)b * NT * 3 * NC;

    if (tid < NHD) qs[tid] = base[(long long)qi * 3 * NC + hh * NHD + tid];
    __syncthreads();

    // scores
    for (int j = tid; j <= qi; j += 256) {
        const float* kr = base + (long long)j * 3 * NC + NC + hh * NHD;
        float d = 0.f;
        #pragma unroll
        for (int u = 0; u < NHD; u++) d += qs[u] * kr[u];
        sc[j] = d * 0.125f;   // 1/sqrt(64)
    }
    __syncthreads();

    // max
    float mx = -1e30f;
    for (int j = tid; j <= qi; j += 256) mx = fmaxf(mx, sc[j]);
    red[tid] = mx; __syncthreads();
    for (int o = 128; o > 0; o >>= 1) { if (tid < o) red[tid] = fmaxf(red[tid], red[tid + o]); __syncthreads(); }
    mx = red[0]; __syncthreads();

    // exp + sum
    float sm = 0.f;
    for (int j = tid; j <= qi; j += 256) { float e = __expf(sc[j] - mx); sc[j] = e; sm += e; }
    red[tid] = sm; __syncthreads();
    for (int o = 128; o > 0; o >>= 1) { if (tid < o) red[tid] += red[tid + o]; __syncthreads(); }
    float inv = 1.0f / red[0];
    __syncthreads();

    // weighted sum of V: 4 groups of 64 lanes
    int g = tid >> 6, d = tid & 63;
    float acc = 0.f;
    for (int j = g; j <= qi; j += 4)
        acc += sc[j] * base[(long long)j * 3 * NC + 2 * NC + hh * NHD + d];
    part[g][d] = acc; __syncthreads();

    if (tid < NHD) {
        float r = (part[0][tid] + part[1][tid] + part[2][tid] + part[3][tid]) * inv;
        y[((long long)(b * NT + qi)) * NC + hh * NHD + tid] = r;
    }
}

// ---------------- loss ----------------
__global__ void k_loss_rows(const float* __restrict__ logits,
                            const int* __restrict__ targets,
                            float* loss_sum, float* loss_cnt)
{
    int row = blockIdx.x;
    int tid = threadIdx.x;
    const float* lr = logits + (long long)row * NV;
    __shared__ float red[256];

    float mx = -1e30f;
    for (int i = tid; i < NV; i += 256) mx = fmaxf(mx, lr[i]);
    red[tid] = mx; __syncthreads();
    for (int o = 128; o > 0; o >>= 1) { if (tid < o) red[tid] = fmaxf(red[tid], red[tid + o]); __syncthreads(); }
    mx = red[0]; __syncthreads();

    float s = 0.f;
    for (int i = tid; i < NV; i += 256) s += __expf(lr[i] - mx);
    red[tid] = s; __syncthreads();
    for (int o = 128; o > 0; o >>= 1) { if (tid < o) red[tid] += red[tid + o]; __syncthreads(); }

    if (tid == 0) {
        int t = targets[row];
        if (t != -1) {
            int tc = t < 0 ? 0 : (t > NV - 1 ? NV - 1 : t);
            float nll = (mx + logf(red[0])) - lr[tc];
            atomicAdd(loss_sum, nll);
            atomicAdd(loss_cnt, 1.0f);
        }
    }
}

__global__ void k_loss_fin(float* dst, const float* s, const float* c)
{
    if (dst) *dst = *s / fmaxf(*c, 1.0f);
}

// ---------------- host orchestration ----------------
extern "C" void kernel_launch(void* const* d_in, const int* in_sizes, int n_in,
                              void* d_out, int out_size)
{
    const int*   idx      = (const int*)  d_in[0];
    const int*   targets  = (const int*)  d_in[1];
    const float* wte      = (const float*)d_in[2];
    const float* wpe      = (const float*)d_in[3];
    const float* ln1_w    = (const float*)d_in[4];
    const float* ln1_b    = (const float*)d_in[5];
    const float* qkv_w    = (const float*)d_in[6];
    const float* qkv_b    = (const float*)d_in[7];
    const float* proj_w   = (const float*)d_in[8];
    const float* proj_b   = (const float*)d_in[9];
    const float* ln2_w    = (const float*)d_in[10];
    const float* ln2_b    = (const float*)d_in[11];
    const float* fc_w     = (const float*)d_in[12];
    const float* fc_b     = (const float*)d_in[13];
    const float* fc2_w    = (const float*)d_in[14];
    const float* fc2_b    = (const float*)d_in[15];
    const float* lnf_w    = (const float*)d_in[16];
    const float* lnf_b    = (const float*)d_in[17];
    const float* head_w   = (const float*)d_in[18];

    float *x, *h, *qkv, *att, *fch, *lscratch, *lsum, *lcnt;
    cudaGetSymbolAddress((void**)&x,   g_x);
    cudaGetSymbolAddress((void**)&h,   g_h);
    cudaGetSymbolAddress((void**)&qkv, g_qkv);
    cudaGetSymbolAddress((void**)&att, g_att);
    cudaGetSymbolAddress((void**)&fch, g_fch);
    cudaGetSymbolAddress((void**)&lscratch, g_logits_scratch);
    cudaGetSymbolAddress((void**)&lsum, g_loss_sum);
    cudaGetSymbolAddress((void**)&lcnt, g_loss_cnt);

    float* logits = (out_size >= NBTV) ? (float*)d_out : lscratch;
    float* loss_dst = nullptr;
    if (out_size >= NBTV + 1)      loss_dst = (float*)d_out + NBTV;
    else if (out_size < NBTV)      loss_dst = (float*)d_out;   // loss-only output

    k_zero_loss<<<1, 1>>>(lsum, lcnt);

    // embedding
    {
        int n = NBT * NC;
        k_embed<<<(n + 255) / 256, 256>>>(idx, wte, wpe, x);
    }

    dim3 attn_grid(NT, NH, NB);

    for (int l = 0; l < NL; l++) {
        // ln1
        k_layernorm<<<NBT, 256>>>(x, ln1_w + l * NC, ln1_b + l * NC, h);
        // qkv = h @ qkv_w[l] + qkv_b[l]
        {
            dim3 grid((3 * NC + 63) / 64, NBT / 64);
            k_gemm<<<grid, 256>>>(h, qkv_w + (long long)l * NC * 3 * NC,
                                  qkv_b + l * 3 * NC, nullptr, qkv,
                                  NBT, 3 * NC, NC, 0);
        }
        // attention
        k_attn<<<attn_grid, 256>>>(qkv, att);
        // x = x + att @ proj_w[l] + proj_b[l]
        {
            dim3 grid((NC + 63) / 64, NBT / 64);
            k_gemm<<<grid, 256>>>(att, proj_w + (long long)l * NC * NC,
                                  proj_b + l * NC, x, x,
                                  NBT, NC, NC, 0);
        }
        // ln2
        k_layernorm<<<NBT, 256>>>(x, ln2_w + l * NC, ln2_b + l * NC, h);
        // fch = gelu(h @ fc_w[l] + fc_b[l])
        {
            dim3 grid((4 * NC + 63) / 64, NBT / 64);
            k_gemm<<<grid, 256>>>(h, fc_w + (long long)l * NC * 4 * NC,
                                  fc_b + l * 4 * NC, nullptr, fch,
                                  NBT, 4 * NC, NC, 1);
        }
        // x = x + fch @ fc2_w[l] + fc2_b[l]
        {
            dim3 grid((NC + 63) / 64, NBT / 64);
            k_gemm<<<grid, 256>>>(fch, fc2_w + (long long)l * 4 * NC * NC,
                                  fc2_b + l * NC, x, x,
                                  NBT, NC, 4 * NC, 0);
        }
    }

    // final layernorm
    k_layernorm<<<NBT, 256>>>(x, lnf_w, lnf_b, h);

    // logits = h @ head_w
    {
        dim3 grid((NV + 63) / 64, NBT / 64);
        k_gemm<<<grid, 256>>>(h, head_w, nullptr, nullptr, logits,
                              NBT, NV, NC, 0);
    }

    // loss
    k_loss_rows<<<NBT, 256>>>(logits, targets, lsum, lcnt);
    k_loss_fin<<<1, 1>>>(loss_dst, lsum, lcnt);
}

// round 2
// speedup vs baseline: 3.5305x; 3.5305x over previous
#include <cuda_runtime.h>
#include <math.h>

// ---------------- problem constants ----------------
#define NB   4
#define NT   1024
#define NC   768
#define NH   12
#define NHD  64
#define NL   12
#define NV   50257
#define NBT  (NB*NT)     // 4096
#define NBTV (NBT*NV)

// ---------------- scratch ----------------
__device__ float g_x  [NBT*NC];
__device__ float g_h  [NBT*NC];
__device__ float g_qkv[NBT*3*NC];
__device__ float g_att[NBT*NC];
__device__ float g_fch[NBT*4*NC];
__device__ float g_logits_scratch[NBTV];
__device__ float g_loss_sum;
__device__ float g_loss_cnt;

__device__ __forceinline__ float gelu_f(float u) {
    return 0.5f * u * (1.0f + tanhf(0.7978845608028654f * (u + 0.044715f * u * u * u)));
}

// ---------------- small kernels ----------------
__global__ void k_zero_loss(float* s, float* c) { *s = 0.f; *c = 0.f; }

__global__ void k_embed(const int* __restrict__ idx,
                        const float* __restrict__ wte,
                        const float* __restrict__ wpe,
                        float* __restrict__ x)
{
    int i = blockIdx.x * blockDim.x + threadIdx.x;
    if (i >= NBT * NC) return;
    int c  = i % NC;
    int bt = i / NC;
    int t  = bt % NT;
    x[i] = wte[(long long)idx[bt] * NC + c] + wpe[t * NC + c];
}

__global__ void k_layernorm(const float* __restrict__ x,
                            const float* __restrict__ w,
                            const float* __restrict__ b,
                            float* __restrict__ out)
{
    int row = blockIdx.x;
    int tid = threadIdx.x;
    const float* xr = x + (long long)row * NC;
    __shared__ float red[256];

    float s = 0.f;
    for (int i = tid; i < NC; i += 256) s += xr[i];
    red[tid] = s; __syncthreads();
    for (int o = 128; o > 0; o >>= 1) { if (tid < o) red[tid] += red[tid + o]; __syncthreads(); }
    float mu = red[0] * (1.0f / NC);
    __syncthreads();

    float v = 0.f;
    for (int i = tid; i < NC; i += 256) { float d = xr[i] - mu; v += d * d; }
    red[tid] = v; __syncthreads();
    for (int o = 128; o > 0; o >>= 1) { if (tid < o) red[tid] += red[tid + o]; __syncthreads(); }
    float rstd = rsqrtf(red[0] * (1.0f / NC) + 1e-5f);
    __syncthreads();

    float* orow = out + (long long)row * NC;
    for (int i = tid; i < NC; i += 256)
        orow[i] = (xr[i] - mu) * rstd * w[i] + b[i];
}

// ---------------- SGEMM 128x128x8, 8x8/thread, double-buffered ----------------
// C[M,N] = A[M,K] @ W[K,N] (+bias)(+res)(gelu). M%128==0, K%8==0; N arbitrary.
__global__ __launch_bounds__(256, 2)
void k_gemm(const float* __restrict__ A,
            const float* __restrict__ W,
            const float* __restrict__ bias,
            const float* __restrict__ res,
            float* __restrict__ C,
            int M, int N, int K, int act)
{
    __shared__ float As[2][8][128];   // [k][m]
    __shared__ float Bs[2][8][128];   // [k][n]

    const int tid = threadIdx.x;
    const int bm = blockIdx.y * 128;
    const int bn = blockIdx.x * 128;
    const int tx = tid & 15;
    const int ty = tid >> 4;

    const int a_row = tid >> 1;           // 0..127
    const int a_k   = (tid & 1) * 4;      // 0 or 4
    const int b_k   = tid >> 5;           // 0..7
    const int b_n   = (tid & 31) * 4;     // 0..124

    const bool n4 = ((N & 3) == 0);

    float acc[8][8];
    #pragma unroll
    for (int i = 0; i < 8; i++)
        #pragma unroll
        for (int j = 0; j < 8; j++) acc[i][j] = 0.f;

    float4 av, bv;
    // prologue: tile 0
    {
        av = *(const float4*)(A + (long long)(bm + a_row) * K + a_k);
        int gn = bn + b_n;
        const float* Wp = W + (long long)b_k * N;
        if (n4 && gn + 3 < N) {
            bv = *(const float4*)(Wp + gn);
        } else {
            bv.x = (gn + 0 < N) ? Wp[gn + 0] : 0.f;
            bv.y = (gn + 1 < N) ? Wp[gn + 1] : 0.f;
            bv.z = (gn + 2 < N) ? Wp[gn + 2] : 0.f;
            bv.w = (gn + 3 < N) ? Wp[gn + 3] : 0.f;
        }
        As[0][a_k + 0][a_row] = av.x;
        As[0][a_k + 1][a_row] = av.y;
        As[0][a_k + 2][a_row] = av.z;
        As[0][a_k + 3][a_row] = av.w;
        *(float4*)&Bs[0][b_k][b_n] = bv;
    }
    __syncthreads();

    int buf = 0;
    for (int k0 = 0; k0 < K; k0 += 8) {
        const int k1 = k0 + 8;
        const bool more = (k1 < K);
        if (more) {
            av = *(const float4*)(A + (long long)(bm + a_row) * K + k1 + a_k);
            int gn = bn + b_n;
            const float* Wp = W + (long long)(k1 + b_k) * N;
            if (n4 && gn + 3 < N) {
                bv = *(const float4*)(Wp + gn);
            } else {
                bv.x = (gn + 0 < N) ? Wp[gn + 0] : 0.f;
                bv.y = (gn + 1 < N) ? Wp[gn + 1] : 0.f;
                bv.z = (gn + 2 < N) ? Wp[gn + 2] : 0.f;
                bv.w = (gn + 3 < N) ? Wp[gn + 3] : 0.f;
            }
        }

        #pragma unroll
        for (int kk = 0; kk < 8; kk++) {
            float4 a0 = *(float4*)&As[buf][kk][ty * 8];
            float4 a1 = *(float4*)&As[buf][kk][ty * 8 + 4];
            float4 b0 = *(float4*)&Bs[buf][kk][tx * 8];
            float4 b1 = *(float4*)&Bs[buf][kk][tx * 8 + 4];
            float ar[8] = {a0.x, a0.y, a0.z, a0.w, a1.x, a1.y, a1.z, a1.w};
            float br[8] = {b0.x, b0.y, b0.z, b0.w, b1.x, b1.y, b1.z, b1.w};
            #pragma unroll
            for (int i = 0; i < 8; i++)
                #pragma unroll
                for (int j = 0; j < 8; j++)
                    acc[i][j] += ar[i] * br[j];
        }

        if (more) {
            int nb = buf ^ 1;
            As[nb][a_k + 0][a_row] = av.x;
            As[nb][a_k + 1][a_row] = av.y;
            As[nb][a_k + 2][a_row] = av.z;
            As[nb][a_k + 3][a_row] = av.w;
            *(float4*)&Bs[nb][b_k][b_n] = bv;
        }
        __syncthreads();
        buf ^= 1;
    }

    // epilogue
    const bool nfull = n4 && (bn + 128 <= N);
    #pragma unroll
    for (int i = 0; i < 8; i++) {
        const int m = bm + ty * 8 + i;
        const long long rowoff = (long long)m * N;
        if (nfull) {
            #pragma unroll
            for (int jj = 0; jj < 8; jj += 4) {
                const int n = bn + tx * 8 + jj;
                float4 v;
                float* vp = &v.x;
                #pragma unroll
                for (int e = 0; e < 4; e++) {
                    float u = acc[i][jj + e];
                    if (bias) u += bias[n + e];
                    if (res)  u += res[rowoff + n + e];
                    if (act == 1) u = gelu_f(u);
                    vp[e] = u;
                }
                *(float4*)(C + rowoff + n) = v;
            }
        } else {
            #pragma unroll
            for (int jj = 0; jj < 8; jj++) {
                const int n = bn + tx * 8 + jj;
                if (n < N) {
                    float u = acc[i][jj];
                    if (bias) u += bias[n];
                    if (res)  u += res[rowoff + n];
                    if (act == 1) u = gelu_f(u);
                    C[rowoff + n] = u;
                }
            }
        }
    }
}

// ---------------- flash attention: 64 queries/block ----------------
// grid (NT/64, NH, NB), 256 threads. smem 48KB.
__global__ __launch_bounds__(256, 4)
void k_attn_flash(const float* __restrict__ qkv, float* __restrict__ y)
{
    __shared__ float Qt[64][64];   // [d][m]
    __shared__ float KP[64][64];   // K^T [d][n], reused as P^T [n][m]
    __shared__ float Vs[64][64];   // [n][d]

    const int tid = threadIdx.x;
    const int tx = tid & 15;
    const int ty = tid >> 4;
    const int q0 = blockIdx.x * 64;
    const int h  = blockIdx.y;
    const int b  = blockIdx.z;

    const float* base = qkv + (long long)b * NT * 3 * NC;
    const int qoff = h * NHD;
    const int koff = NC + h * NHD;
    const int voff = 2 * NC + h * NHD;

    // load Q transposed
    #pragma unroll
    for (int r = 0; r < 4; r++) {
        int idx = tid + r * 256;
        int m  = idx >> 4;
        int d4 = (idx & 15) << 2;
        float4 v = *(const float4*)(base + (long long)(q0 + m) * 3 * NC + qoff + d4);
        Qt[d4 + 0][m] = v.x; Qt[d4 + 1][m] = v.y;
        Qt[d4 + 2][m] = v.z; Qt[d4 + 3][m] = v.w;
    }

    float o[4][4];
    float mi[4], li[4];
    #pragma unroll
    for (int i = 0; i < 4; i++) {
        mi[i] = -1e30f; li[i] = 0.f;
        #pragma unroll
        for (int j = 0; j < 4; j++) o[i][j] = 0.f;
    }

    const int ntiles = blockIdx.x + 1;
    for (int tj = 0; tj < ntiles; tj++) {
        const int j0 = tj * 64;
        __syncthreads();   // protect KP/Vs from previous-iter readers (also covers Qt on iter 0)

        #pragma unroll
        for (int r = 0; r < 4; r++) {
            int idx = tid + r * 256;
            int n  = idx >> 4;
            int d4 = (idx & 15) << 2;
            const float* rowp = base + (long long)(j0 + n) * 3 * NC;
            float4 kv = *(const float4*)(rowp + koff + d4);
            KP[d4 + 0][n] = kv.x; KP[d4 + 1][n] = kv.y;
            KP[d4 + 2][n] = kv.z; KP[d4 + 3][n] = kv.w;
            *(float4*)&Vs[n][d4] = *(const float4*)(rowp + voff + d4);
        }
        __syncthreads();

        // S = Q @ K^T
        float s[4][4];
        #pragma unroll
        for (int i = 0; i < 4; i++)
            #pragma unroll
            for (int j = 0; j < 4; j++) s[i][j] = 0.f;

        #pragma unroll
        for (int d = 0; d < 64; d++) {
            float4 a0 = *(float4*)&Qt[d][ty * 4];
            float4 b0 = *(float4*)&KP[d][tx * 4];
            float ar[4] = {a0.x, a0.y, a0.z, a0.w};
            float br[4] = {b0.x, b0.y, b0.z, b0.w};
            #pragma unroll
            for (int i = 0; i < 4; i++)
                #pragma unroll
                for (int j = 0; j < 4; j++)
                    s[i][j] += ar[i] * br[j];
        }

        const bool diag = (j0 == q0);
        #pragma unroll
        for (int i = 0; i < 4; i++) {
            const int q = q0 + ty * 4 + i;
            #pragma unroll
            for (int j = 0; j < 4; j++) {
                float v = s[i][j] * 0.125f;
                if (diag && (j0 + tx * 4 + j) > q) v = -1e30f;
                s[i][j] = v;
            }
        }

        __syncthreads();   // done reading KP as K^T; reuse as P^T

        #pragma unroll
        for (int i = 0; i < 4; i++) {
            float rm = fmaxf(fmaxf(s[i][0], s[i][1]), fmaxf(s[i][2], s[i][3]));
            #pragma unroll
            for (int off = 1; off < 16; off <<= 1)
                rm = fmaxf(rm, __shfl_xor_sync(0xffffffffu, rm, off));
            float mnew = fmaxf(mi[i], rm);
            float corr = __expf(mi[i] - mnew);
            float rs = 0.f;
            #pragma unroll
            for (int j = 0; j < 4; j++) {
                float p = __expf(s[i][j] - mnew);
                KP[tx * 4 + j][ty * 4 + i] = p;
                rs += p;
            }
            #pragma unroll
            for (int off = 1; off < 16; off <<= 1)
                rs += __shfl_xor_sync(0xffffffffu, rs, off);
            li[i] = li[i] * corr + rs;
            mi[i] = mnew;
            #pragma unroll
            for (int j = 0; j < 4; j++) o[i][j] *= corr;
        }
        __syncthreads();

        // O += P @ V
        #pragma unroll
        for (int n = 0; n < 64; n++) {
            float4 a0 = *(float4*)&KP[n][ty * 4];
            float4 b0 = *(float4*)&Vs[n][tx * 4];
            float ar[4] = {a0.x, a0.y, a0.z, a0.w};
            float br[4] = {b0.x, b0.y, b0.z, b0.w};
            #pragma unroll
            for (int i = 0; i < 4; i++)
                #pragma unroll
                for (int j = 0; j < 4; j++)
                    o[i][j] += ar[i] * br[j];
        }
    }

    #pragma unroll
    for (int i = 0; i < 4; i++) {
        const int q = q0 + ty * 4 + i;
        const float inv = 1.0f / li[i];
        float4 v = make_float4(o[i][0] * inv, o[i][1] * inv, o[i][2] * inv, o[i][3] * inv);
        *(float4*)(y + (long long)(b * NT + q) * NC + h * NHD + tx * 4) = v;
    }
}

// ---------------- loss ----------------
__global__ void k_loss_rows(const float* __restrict__ logits,
                            const int* __restrict__ targets,
                            float* loss_sum, float* loss_cnt)
{
    int row = blockIdx.x;
    int tid = threadIdx.x;
    const float* lr = logits + (long long)row * NV;
    __shared__ float red[256];

    float mx = -1e30f;
    for (int i = tid; i < NV; i += 256) mx = fmaxf(mx, lr[i]);
    red[tid] = mx; __syncthreads();
    for (int o = 128; o > 0; o >>= 1) { if (tid < o) red[tid] = fmaxf(red[tid], red[tid + o]); __syncthreads(); }
    mx = red[0]; __syncthreads();

    float s = 0.f;
    for (int i = tid; i < NV; i += 256) s += __expf(lr[i] - mx);
    red[tid] = s; __syncthreads();
    for (int o = 128; o > 0; o >>= 1) { if (tid < o) red[tid] += red[tid + o]; __syncthreads(); }

    if (tid == 0) {
        int t = targets[row];
        if (t != -1) {
            int tc = t < 0 ? 0 : (t > NV - 1 ? NV - 1 : t);
            float nll = (mx + logf(red[0])) - lr[tc];
            atomicAdd(loss_sum, nll);
            atomicAdd(loss_cnt, 1.0f);
        }
    }
}

__global__ void k_loss_fin(float* dst, const float* s, const float* c)
{
    if (dst) *dst = *s / fmaxf(*c, 1.0f);
}

// ---------------- host orchestration ----------------
extern "C" void kernel_launch(void* const* d_in, const int* in_sizes, int n_in,
                              void* d_out, int out_size)
{
    const int*   idx      = (const int*)  d_in[0];
    const int*   targets  = (const int*)  d_in[1];
    const float* wte      = (const float*)d_in[2];
    const float* wpe      = (const float*)d_in[3];
    const float* ln1_w    = (const float*)d_in[4];
    const float* ln1_b    = (const float*)d_in[5];
    const float* qkv_w    = (const float*)d_in[6];
    const float* qkv_b    = (const float*)d_in[7];
    const float* proj_w   = (const float*)d_in[8];
    const float* proj_b   = (const float*)d_in[9];
    const float* ln2_w    = (const float*)d_in[10];
    const float* ln2_b    = (const float*)d_in[11];
    const float* fc_w     = (const float*)d_in[12];
    const float* fc_b     = (const float*)d_in[13];
    const float* fc2_w    = (const float*)d_in[14];
    const float* fc2_b    = (const float*)d_in[15];
    const float* lnf_w    = (const float*)d_in[16];
    const float* lnf_b    = (const float*)d_in[17];
    const float* head_w   = (const float*)d_in[18];

    float *x, *h, *qkv, *att, *fch, *lscratch, *lsum, *lcnt;
    cudaGetSymbolAddress((void**)&x,   g_x);
    cudaGetSymbolAddress((void**)&h,   g_h);
    cudaGetSymbolAddress((void**)&qkv, g_qkv);
    cudaGetSymbolAddress((void**)&att, g_att);
    cudaGetSymbolAddress((void**)&fch, g_fch);
    cudaGetSymbolAddress((void**)&lscratch, g_logits_scratch);
    cudaGetSymbolAddress((void**)&lsum, g_loss_sum);
    cudaGetSymbolAddress((void**)&lcnt, g_loss_cnt);

    float* logits = (out_size >= NBTV) ? (float*)d_out : lscratch;
    float* loss_dst = nullptr;
    if (out_size >= NBTV + 1)      loss_dst = (float*)d_out + NBTV;
    else if (out_size < NBTV)      loss_dst = (float*)d_out;

    k_zero_loss<<<1, 1>>>(lsum, lcnt);

    {
        int n = NBT * NC;
        k_embed<<<(n + 255) / 256, 256>>>(idx, wte, wpe, x);
    }

    dim3 attn_grid(NT / 64, NH, NB);

    for (int l = 0; l < NL; l++) {
        k_layernorm<<<NBT, 256>>>(x, ln1_w + l * NC, ln1_b + l * NC, h);
        {
            dim3 grid((3 * NC + 127) / 128, NBT / 128);
            k_gemm<<<grid, 256>>>(h, qkv_w + (long long)l * NC * 3 * NC,
                                  qkv_b + l * 3 * NC, nullptr, qkv,
                                  NBT, 3 * NC, NC, 0);
        }
        k_attn_flash<<<attn_grid, 256>>>(qkv, att);
        {
            dim3 grid((NC + 127) / 128, NBT / 128);
            k_gemm<<<grid, 256>>>(att, proj_w + (long long)l * NC * NC,
                                  proj_b + l * NC, x, x,
                                  NBT, NC, NC, 0);
        }
        k_layernorm<<<NBT, 256>>>(x, ln2_w + l * NC, ln2_b + l * NC, h);
        {
            dim3 grid((4 * NC + 127) / 128, NBT / 128);
            k_gemm<<<grid, 256>>>(h, fc_w + (long long)l * NC * 4 * NC,
                                  fc_b + l * 4 * NC, nullptr, fch,
                                  NBT, 4 * NC, NC, 1);
        }
        {
            dim3 grid((NC + 127) / 128, NBT / 128);
            k_gemm<<<grid, 256>>>(fch, fc2_w + (long long)l * 4 * NC * NC,
                                  fc2_b + l * NC, x, x,
                                  NBT, NC, 4 * NC, 0);
        }
    }

    k_layernorm<<<NBT, 256>>>(x, lnf_w, lnf_b, h);

    {
        dim3 grid((NV + 127) / 128, NBT / 128);
        k_gemm<<<grid, 256>>>(h, head_w, nullptr, nullptr, logits,
                              NBT, NV, NC, 0);
    }

    k_loss_rows<<<NBT, 256>>>(logits, targets, lsum, lcnt);
    k_loss_fin<<<1, 1>>>(loss_dst, lsum, lcnt);
}

// round 3
// speedup vs baseline: 6.9100x; 1.9572x over previous
#include <cuda_runtime.h>
#include <math.h>
#include <stdint.h>

// ---------------- problem constants ----------------
#define NB   4
#define NT   1024
#define NC   768
#define NH   12
#define NHD  64
#define NL   12
#define NV   50257
#define NBT  (NB*NT)     // 4096
#define NBTV (NBT*NV)

// ---------------- scratch ----------------
__device__ float g_x  [NBT*NC];
__device__ float g_h  [NBT*NC];
__device__ float g_qkv[NBT*3*NC];
__device__ float g_att[NBT*NC];
__device__ float g_fch[NBT*4*NC];
__device__ float g_logits_scratch[NBTV];
__device__ float g_loss_sum;
__device__ float g_loss_cnt;

__device__ __forceinline__ float gelu_f(float u) {
    return 0.5f * u * (1.0f + tanhf(0.7978845608028654f * (u + 0.044715f * u * u * u)));
}

__device__ __forceinline__ uint32_t f2t(float x) {
    uint32_t u;
    asm("cvt.rna.tf32.f32 %0, %1;" : "=r"(u) : "f"(x));
    return u;
}

__device__ __forceinline__ void mma_tf32(float* c, const uint32_t* a, const uint32_t* b) {
    asm volatile(
        "mma.sync.aligned.m16n8k8.row.col.f32.tf32.tf32.f32 "
        "{%0,%1,%2,%3}, {%4,%5,%6,%7}, {%8,%9}, {%0,%1,%2,%3};"
        : "+f"(c[0]), "+f"(c[1]), "+f"(c[2]), "+f"(c[3])
        : "r"(a[0]), "r"(a[1]), "r"(a[2]), "r"(a[3]), "r"(b[0]), "r"(b[1]));
}

// ---------------- small kernels ----------------
__global__ void k_zero_loss(float* s, float* c) { *s = 0.f; *c = 0.f; }

__global__ void k_embed(const int* __restrict__ idx,
                        const float* __restrict__ wte,
                        const float* __restrict__ wpe,
                        float* __restrict__ x)
{
    int i = blockIdx.x * blockDim.x + threadIdx.x;
    if (i >= NBT * NC) return;
    int c  = i % NC;
    int bt = i / NC;
    int t  = bt % NT;
    x[i] = wte[(long long)idx[bt] * NC + c] + wpe[t * NC + c];
}

__global__ void k_layernorm(const float* __restrict__ x,
                            const float* __restrict__ w,
                            const float* __restrict__ b,
                            float* __restrict__ out)
{
    int row = blockIdx.x;
    int tid = threadIdx.x;
    const float* xr = x + (long long)row * NC;
    __shared__ float red[256];

    float s = 0.f;
    for (int i = tid; i < NC; i += 256) s += xr[i];
    red[tid] = s; __syncthreads();
    for (int o = 128; o > 0; o >>= 1) { if (tid < o) red[tid] += red[tid + o]; __syncthreads(); }
    float mu = red[0] * (1.0f / NC);
    __syncthreads();

    float v = 0.f;
    for (int i = tid; i < NC; i += 256) { float d = xr[i] - mu; v += d * d; }
    red[tid] = v; __syncthreads();
    for (int o = 128; o > 0; o >>= 1) { if (tid < o) red[tid] += red[tid + o]; __syncthreads(); }
    float rstd = rsqrtf(red[0] * (1.0f / NC) + 1e-5f);
    __syncthreads();

    float* orow = out + (long long)row * NC;
    for (int i = tid; i < NC; i += 256)
        orow[i] = (xr[i] - mu) * rstd * w[i] + b[i];
}

// ---------------- tf32 tensor-core GEMM ----------------
// C[M,N] = A[M,K] @ W[K,N] (+bias)(+res)(gelu). M%128==0, K%16==0. N arbitrary.
// 128x128x16 tile, 256 threads (8 warps), warp = 64x32, double-buffered smem.
#define BM 128
#define BN 128
#define BK 16
#define ASTR 20     // 20 mod 32: g*20+tig hits all 32 banks -> conflict-free A frags
#define BSTR 136    // 136 mod 32 = 8: tig*8+g hits all 32 banks -> conflict-free B frags

__global__ __launch_bounds__(256, 2)
void k_gemm_tc(const float* __restrict__ A,
               const float* __restrict__ W,
               const float* __restrict__ bias,
               const float* __restrict__ res,
               float* __restrict__ C,
               int M, int N, int K, int act)
{
    __shared__ uint32_t As[2][BM][ASTR];
    __shared__ uint32_t Bs[2][BK][BSTR];

    const int tid  = threadIdx.x;
    const int lane = tid & 31;
    const int w    = tid >> 5;
    const int bm   = blockIdx.y * BM;
    const int bn   = blockIdx.x * BN;
    const int wm   = (w & 1) * 64;
    const int wn   = (w >> 1) * 32;
    const int g    = lane >> 2;
    const int tig  = lane & 3;
    const bool n4  = ((N & 3) == 0);

    // global load mapping
    const int ar = tid >> 1;           // A row 0..127
    const int ak = (tid & 1) * 8;      // A k base 0 or 8
    const int brow = tid >> 4;         // B k row 0..15
    const int bc   = (tid & 15) * 8;   // B n base 0..120

    float acc[16][4];
    #pragma unroll
    for (int i = 0; i < 16; i++)
        #pragma unroll
        for (int j = 0; j < 4; j++) acc[i][j] = 0.f;

    float a_pre[8], b_pre[8];

    // ---- prologue load (k0 = 0) ----
    {
        const float* Ap = A + (long long)(bm + ar) * K + ak;
        *(float4*)(a_pre)     = *(const float4*)(Ap);
        *(float4*)(a_pre + 4) = *(const float4*)(Ap + 4);
        const float* Wp = W + (long long)brow * N;
        int gn = bn + bc;
        if (n4 && gn + 7 < N) {
            *(float4*)(b_pre)     = *(const float4*)(Wp + gn);
            *(float4*)(b_pre + 4) = *(const float4*)(Wp + gn + 4);
        } else {
            #pragma unroll
            for (int e = 0; e < 8; e++)
                b_pre[e] = (gn + e < N) ? Wp[gn + e] : 0.f;
        }
    }
    {
        uint4 u0 = make_uint4(f2t(a_pre[0]), f2t(a_pre[1]), f2t(a_pre[2]), f2t(a_pre[3]));
        uint4 u1 = make_uint4(f2t(a_pre[4]), f2t(a_pre[5]), f2t(a_pre[6]), f2t(a_pre[7]));
        *(uint4*)&As[0][ar][ak]     = u0;
        *(uint4*)&As[0][ar][ak + 4] = u1;
        uint4 v0 = make_uint4(f2t(b_pre[0]), f2t(b_pre[1]), f2t(b_pre[2]), f2t(b_pre[3]));
        uint4 v1 = make_uint4(f2t(b_pre[4]), f2t(b_pre[5]), f2t(b_pre[6]), f2t(b_pre[7]));
        *(uint4*)&Bs[0][brow][bc]     = v0;
        *(uint4*)&Bs[0][brow][bc + 4] = v1;
    }
    __syncthreads();

    int buf = 0;
    for (int k0 = 0; k0 < K; k0 += BK) {
        const bool more = (k0 + BK < K);
        if (more) {
            const int k1 = k0 + BK;
            const float* Ap = A + (long long)(bm + ar) * K + k1 + ak;
            *(float4*)(a_pre)     = *(const float4*)(Ap);
            *(float4*)(a_pre + 4) = *(const float4*)(Ap + 4);
            const float* Wp = W + (long long)(k1 + brow) * N;
            int gn = bn + bc;
            if (n4 && gn + 7 < N) {
                *(float4*)(b_pre)     = *(const float4*)(Wp + gn);
                *(float4*)(b_pre + 4) = *(const float4*)(Wp + gn + 4);
            } else {
                #pragma unroll
                for (int e = 0; e < 8; e++)
                    b_pre[e] = (gn + e < N) ? Wp[gn + e] : 0.f;
            }
        }

        // ---- compute 2 k-steps of 8 ----
        #pragma unroll
        for (int ks = 0; ks < 2; ks++) {
            const int kb = ks * 8;
            uint32_t af[4][4], bf[4][2];
            #pragma unroll
            for (int mt = 0; mt < 4; mt++) {
                const int row = wm + mt * 16 + g;
                af[mt][0] = As[buf][row][kb + tig];
                af[mt][1] = As[buf][row + 8][kb + tig];
                af[mt][2] = As[buf][row][kb + tig + 4];
                af[mt][3] = As[buf][row + 8][kb + tig + 4];
            }
            #pragma unroll
            for (int nt = 0; nt < 4; nt++) {
                const int col = wn + nt * 8 + g;
                bf[nt][0] = Bs[buf][kb + tig][col];
                bf[nt][1] = Bs[buf][kb + tig + 4][col];
            }
            #pragma unroll
            for (int mt = 0; mt < 4; mt++)
                #pragma unroll
                for (int nt = 0; nt < 4; nt++)
                    mma_tf32(acc[mt * 4 + nt], af[mt], bf[nt]);
        }

        if (more) {
            const int nb = buf ^ 1;
            uint4 u0 = make_uint4(f2t(a_pre[0]), f2t(a_pre[1]), f2t(a_pre[2]), f2t(a_pre[3]));
            uint4 u1 = make_uint4(f2t(a_pre[4]), f2t(a_pre[5]), f2t(a_pre[6]), f2t(a_pre[7]));
            *(uint4*)&As[nb][ar][ak]     = u0;
            *(uint4*)&As[nb][ar][ak + 4] = u1;
            uint4 v0 = make_uint4(f2t(b_pre[0]), f2t(b_pre[1]), f2t(b_pre[2]), f2t(b_pre[3]));
            uint4 v1 = make_uint4(f2t(b_pre[4]), f2t(b_pre[5]), f2t(b_pre[6]), f2t(b_pre[7]));
            *(uint4*)&Bs[nb][brow][bc]     = v0;
            *(uint4*)&Bs[nb][brow][bc + 4] = v1;
        }
        __syncthreads();
        buf ^= 1;
    }

    // ---- epilogue ----
    #pragma unroll
    for (int mt = 0; mt < 4; mt++) {
        #pragma unroll
        for (int nt = 0; nt < 4; nt++) {
            const float* c = acc[mt * 4 + nt];
            const int n = bn + wn + nt * 8 + tig * 2;
            #pragma unroll
            for (int half = 0; half < 2; half++) {
                const int m = bm + wm + mt * 16 + g + half * 8;
                const long long rowoff = (long long)m * N;
                float v0 = c[half * 2 + 0];
                float v1 = c[half * 2 + 1];
                if (n4) {
                    if (bias) { v0 += bias[n]; v1 += bias[n + 1]; }
                    if (res)  { v0 += res[rowoff + n]; v1 += res[rowoff + n + 1]; }
                    if (act == 1) { v0 = gelu_f(v0); v1 = gelu_f(v1); }
                    *(float2*)(C + rowoff + n) = make_float2(v0, v1);
                } else {
                    if (n < N) {
                        float u = v0;
                        if (bias) u += bias[n];
                        if (res)  u += res[rowoff + n];
                        if (act == 1) u = gelu_f(u);
                        C[rowoff + n] = u;
                    }
                    if (n + 1 < N) {
                        float u = v1;
                        if (bias) u += bias[n + 1];
                        if (res)  u += res[rowoff + n + 1];
                        if (act == 1) u = gelu_f(u);
                        C[rowoff + n + 1] = u;
                    }
                }
            }
        }
    }
}

// ---------------- flash attention: 64 queries/block ----------------
__global__ __launch_bounds__(256, 4)
void k_attn_flash(const float* __restrict__ qkv, float* __restrict__ y)
{
    __shared__ float Qt[64][64];
    __shared__ float KP[64][64];
    __shared__ float Vs[64][64];

    const int tid = threadIdx.x;
    const int tx = tid & 15;
    const int ty = tid >> 4;
    const int q0 = blockIdx.x * 64;
    const int h  = blockIdx.y;
    const int b  = blockIdx.z;

    const float* base = qkv + (long long)b * NT * 3 * NC;
    const int qoff = h * NHD;
    const int koff = NC + h * NHD;
    const int voff = 2 * NC + h * NHD;

    #pragma unroll
    for (int r = 0; r < 4; r++) {
        int idx = tid + r * 256;
        int m  = idx >> 4;
        int d4 = (idx & 15) << 2;
        float4 v = *(const float4*)(base + (long long)(q0 + m) * 3 * NC + qoff + d4);
        Qt[d4 + 0][m] = v.x; Qt[d4 + 1][m] = v.y;
        Qt[d4 + 2][m] = v.z; Qt[d4 + 3][m] = v.w;
    }

    float o[4][4];
    float mi[4], li[4];
    #pragma unroll
    for (int i = 0; i < 4; i++) {
        mi[i] = -1e30f; li[i] = 0.f;
        #pragma unroll
        for (int j = 0; j < 4; j++) o[i][j] = 0.f;
    }

    const int ntiles = blockIdx.x + 1;
    for (int tj = 0; tj < ntiles; tj++) {
        const int j0 = tj * 64;
        __syncthreads();

        #pragma unroll
        for (int r = 0; r < 4; r++) {
            int idx = tid + r * 256;
            int n  = idx >> 4;
            int d4 = (idx & 15) << 2;
            const float* rowp = base + (long long)(j0 + n) * 3 * NC;
            float4 kv = *(const float4*)(rowp + koff + d4);
            KP[d4 + 0][n] = kv.x; KP[d4 + 1][n] = kv.y;
            KP[d4 + 2][n] = kv.z; KP[d4 + 3][n] = kv.w;
            *(float4*)&Vs[n][d4] = *(const float4*)(rowp + voff + d4);
        }
        __syncthreads();

        float s[4][4];
        #pragma unroll
        for (int i = 0; i < 4; i++)
            #pragma unroll
            for (int j = 0; j < 4; j++) s[i][j] = 0.f;

        #pragma unroll
        for (int d = 0; d < 64; d++) {
            float4 a0 = *(float4*)&Qt[d][ty * 4];
            float4 b0 = *(float4*)&KP[d][tx * 4];
            float ar[4] = {a0.x, a0.y, a0.z, a0.w};
            float br[4] = {b0.x, b0.y, b0.z, b0.w};
            #pragma unroll
            for (int i = 0; i < 4; i++)
                #pragma unroll
                for (int j = 0; j < 4; j++)
                    s[i][j] += ar[i] * br[j];
        }

        const bool diag = (j0 == q0);
        #pragma unroll
        for (int i = 0; i < 4; i++) {
            const int q = q0 + ty * 4 + i;
            #pragma unroll
            for (int j = 0; j < 4; j++) {
                float v = s[i][j] * 0.125f;
                if (diag && (j0 + tx * 4 + j) > q) v = -1e30f;
                s[i][j] = v;
            }
        }

        __syncthreads();

        #pragma unroll
        for (int i = 0; i < 4; i++) {
            float rm = fmaxf(fmaxf(s[i][0], s[i][1]), fmaxf(s[i][2], s[i][3]));
            #pragma unroll
            for (int off = 1; off < 16; off <<= 1)
                rm = fmaxf(rm, __shfl_xor_sync(0xffffffffu, rm, off));
            float mnew = fmaxf(mi[i], rm);
            float corr = __expf(mi[i] - mnew);
            float rs = 0.f;
            #pragma unroll
            for (int j = 0; j < 4; j++) {
                float p = __expf(s[i][j] - mnew);
                KP[tx * 4 + j][ty * 4 + i] = p;
                rs += p;
            }
            #pragma unroll
            for (int off = 1; off < 16; off <<= 1)
                rs += __shfl_xor_sync(0xffffffffu, rs, off);
            li[i] = li[i] * corr + rs;
            mi[i] = mnew;
            #pragma unroll
            for (int j = 0; j < 4; j++) o[i][j] *= corr;
        }
        __syncthreads();

        #pragma unroll
        for (int n = 0; n < 64; n++) {
            float4 a0 = *(float4*)&KP[n][ty * 4];
            float4 b0 = *(float4*)&Vs[n][tx * 4];
            float ar[4] = {a0.x, a0.y, a0.z, a0.w};
            float br[4] = {b0.x, b0.y, b0.z, b0.w};
            #pragma unroll
            for (int i = 0; i < 4; i++)
                #pragma unroll
                for (int j = 0; j < 4; j++)
                    o[i][j] += ar[i] * br[j];
        }
    }

    #pragma unroll
    for (int i = 0; i < 4; i++) {
        const int q = q0 + ty * 4 + i;
        const float inv = 1.0f / li[i];
        float4 v = make_float4(o[i][0] * inv, o[i][1] * inv, o[i][2] * inv, o[i][3] * inv);
        *(float4*)(y + (long long)(b * NT + q) * NC + h * NHD + tx * 4) = v;
    }
}

// ---------------- loss ----------------
__global__ void k_loss_rows(const float* __restrict__ logits,
                            const int* __restrict__ targets,
                            float* loss_sum, float* loss_cnt)
{
    int row = blockIdx.x;
    int tid = threadIdx.x;
    const float* lr = logits + (long long)row * NV;
    __shared__ float red[256];

    float mx = -1e30f;
    for (int i = tid; i < NV; i += 256) mx = fmaxf(mx, lr[i]);
    red[tid] = mx; __syncthreads();
    for (int o = 128; o > 0; o >>= 1) { if (tid < o) red[tid] = fmaxf(red[tid], red[tid + o]); __syncthreads(); }
    mx = red[0]; __syncthreads();

    float s = 0.f;
    for (int i = tid; i < NV; i += 256) s += __expf(lr[i] - mx);
    red[tid] = s; __syncthreads();
    for (int o = 128; o > 0; o >>= 1) { if (tid < o) red[tid] += red[tid + o]; __syncthreads(); }

    if (tid == 0) {
        int t = targets[row];
        if (t != -1) {
            int tc = t < 0 ? 0 : (t > NV - 1 ? NV - 1 : t);
            float nll = (mx + logf(red[0])) - lr[tc];
            atomicAdd(loss_sum, nll);
            atomicAdd(loss_cnt, 1.0f);
        }
    }
}

__global__ void k_loss_fin(float* dst, const float* s, const float* c)
{
    if (dst) *dst = *s / fmaxf(*c, 1.0f);
}

// ---------------- host orchestration ----------------
extern "C" void kernel_launch(void* const* d_in, const int* in_sizes, int n_in,
                              void* d_out, int out_size)
{
    const int*   idx      = (const int*)  d_in[0];
    const int*   targets  = (const int*)  d_in[1];
    const float* wte      = (const float*)d_in[2];
    const float* wpe      = (const float*)d_in[3];
    const float* ln1_w    = (const float*)d_in[4];
    const float* ln1_b    = (const float*)d_in[5];
    const float* qkv_w    = (const float*)d_in[6];
    const float* qkv_b    = (const float*)d_in[7];
    const float* proj_w   = (const float*)d_in[8];
    const float* proj_b   = (const float*)d_in[9];
    const float* ln2_w    = (const float*)d_in[10];
    const float* ln2_b    = (const float*)d_in[11];
    const float* fc_w     = (const float*)d_in[12];
    const float* fc_b     = (const float*)d_in[13];
    const float* fc2_w    = (const float*)d_in[14];
    const float* fc2_b    = (const float*)d_in[15];
    const float* lnf_w    = (const float*)d_in[16];
    const float* lnf_b    = (const float*)d_in[17];
    const float* head_w   = (const float*)d_in[18];

    float *x, *h, *qkv, *att, *fch, *lscratch, *lsum, *lcnt;
    cudaGetSymbolAddress((void**)&x,   g_x);
    cudaGetSymbolAddress((void**)&h,   g_h);
    cudaGetSymbolAddress((void**)&qkv, g_qkv);
    cudaGetSymbolAddress((void**)&att, g_att);
    cudaGetSymbolAddress((void**)&fch, g_fch);
    cudaGetSymbolAddress((void**)&lscratch, g_logits_scratch);
    cudaGetSymbolAddress((void**)&lsum, g_loss_sum);
    cudaGetSymbolAddress((void**)&lcnt, g_loss_cnt);

    float* logits = (out_size >= NBTV) ? (float*)d_out : lscratch;
    float* loss_dst = nullptr;
    if (out_size >= NBTV + 1)      loss_dst = (float*)d_out + NBTV;
    else if (out_size < NBTV)      loss_dst = (float*)d_out;

    k_zero_loss<<<1, 1>>>(lsum, lcnt);

    {
        int n = NBT * NC;
        k_embed<<<(n + 255) / 256, 256>>>(idx, wte, wpe, x);
    }

    dim3 attn_grid(NT / 64, NH, NB);

    for (int l = 0; l < NL; l++) {
        k_layernorm<<<NBT, 256>>>(x, ln1_w + l * NC, ln1_b + l * NC, h);
        {
            dim3 grid((3 * NC + 127) / 128, NBT / 128);
            k_gemm_tc<<<grid, 256>>>(h, qkv_w + (long long)l * NC * 3 * NC,
                                     qkv_b + l * 3 * NC, nullptr, qkv,
                                     NBT, 3 * NC, NC, 0);
        }
        k_attn_flash<<<attn_grid, 256>>>(qkv, att);
        {
            dim3 grid((NC + 127) / 128, NBT / 128);
            k_gemm_tc<<<grid, 256>>>(att, proj_w + (long long)l * NC * NC,
                                     proj_b + l * NC, x, x,
                                     NBT, NC, NC, 0);
        }
        k_layernorm<<<NBT, 256>>>(x, ln2_w + l * NC, ln2_b + l * NC, h);
        {
            dim3 grid((4 * NC + 127) / 128, NBT / 128);
            k_gemm_tc<<<grid, 256>>>(h, fc_w + (long long)l * NC * 4 * NC,
                                     fc_b + l * 4 * NC, nullptr, fch,
                                     NBT, 4 * NC, NC, 1);
        }
        {
            dim3 grid((NC + 127) / 128, NBT / 128);
            k_gemm_tc<<<grid, 256>>>(fch, fc2_w + (long long)l * 4 * NC * NC,
                                     fc2_b + l * NC, x, x,
                                     NBT, NC, 4 * NC, 0);
        }
    }

    k_layernorm<<<NBT, 256>>>(x, lnf_w, lnf_b, h);

    {
        dim3 grid((NV + 127) / 128, NBT / 128);
        k_gemm_tc<<<grid, 256>>>(h, head_w, nullptr, nullptr, logits,
                                 NBT, NV, NC, 0);
    }

    k_loss_rows<<<NBT, 256>>>(logits, targets, lsum, lcnt);
    k_loss_fin<<<1, 1>>>(loss_dst, lsum, lcnt);
}